// round 10
// baseline (speedup 1.0000x reference)
#include <cuda_runtime.h>
#include <math.h>

#define NNODES 50000
#define NEDGES 800000
#define EALL   850000          // edges + self loops
#define F_IN   32
#define CELL_DIM 16
#define D_IN   48              // F_IN + CELL_DIM
#define XCOLS  33              // F_IN + 1 (cell id column)
#define C      64
#define NEG_SLOPE 0.2f
#define OFFB   ((NNODES + 255) / 256)    // 196 offset blocks

// ---------------- scratch ----------------------------------------------------
__device__ int   g_deg[NNODES + 1];      // [NNODES] doubles as global cursor
__device__ int   g_off[NNODES];
__device__ int   g_cursor[NNODES];
__device__ int   g_csrc[EALL];
__device__ float g_h0[NNODES * 128];     // layer0 transformed [N, head0|head1]
__device__ float g_as0[NNODES * 2];
__device__ float g_ad0[NNODES * 2];
__device__ float g_h1[NNODES * C];
__device__ float g_as1[NNODES];
__device__ float g_ad1[NNODES];
__device__ float g_ws0[D_IN * 2];        // W0 @ a_src0   [k][h]
__device__ float g_wd0[D_IN * 2];        // W0 @ a_dst0   [k][h]

__device__ __forceinline__ float warpSum(float v) {
#pragma unroll
    for (int o = 16; o; o >>= 1) v += __shfl_xor_sync(0xffffffffu, v, o);
    return v;
}

__device__ __forceinline__ float lrelu(float e) {
    return e > 0.f ? e : NEG_SLOPE * e;
}

// ---------------- CSR build --------------------------------------------------
__global__ void k_count(const int* __restrict__ ei) {
    int i = blockIdx.x * blockDim.x + threadIdx.x;
    if (i >= EALL) return;
    int d = (i < NEDGES) ? ei[NEDGES + i] : (i - NEDGES);
    atomicAdd(&g_deg[d], 1);
}

// Atomic segment assignment (order-independent); block OFFB additionally
// precomputes ws0/wd0 = W0 @ a_{src,dst}0 (folded to avoid an extra launch).
__global__ void k_offsets(const float* __restrict__ W0,
                          const float* __restrict__ as0,
                          const float* __restrict__ ad0) {
    int b = blockIdx.x, tid = threadIdx.x;
    if (b < OFFB) {
        int i = b * 256 + tid;
        if (i >= NNODES) return;
        int d = g_deg[i];
        int o = atomicAdd(&g_deg[NNODES], d);
        g_off[i] = o;
        g_cursor[i] = o;
    } else if (tid < 192) {
        int idx = tid % 96, which = tid / 96;       // 96 = D_IN*2
        int k = idx >> 1, h = idx & 1;
        const float* a = which ? ad0 : as0;
        float s = 0.f;
#pragma unroll
        for (int c = 0; c < 64; c++)
            s = fmaf(W0[k * 128 + h * 64 + c], a[h * 64 + c], s);
        if (which) g_wd0[idx] = s; else g_ws0[idx] = s;
    }
}

__global__ void k_fill(const int* __restrict__ ei) {
    int i = blockIdx.x * blockDim.x + threadIdx.x;
    if (i >= EALL) return;
    int s, d;
    if (i < NEDGES) { s = ei[i]; d = ei[NEDGES + i]; }
    else            { s = i - NEDGES; d = s; }
    int p = atomicAdd(&g_cursor[d], 1);
    g_csrc[p] = s;
}

// ---------------- layer0 node transform: feat[48] @ W0[48,128] ---------------
// ONE tile (8 nodes) per block — block-level parallelism hides staging
// latency (grid-stride serialized it). Thread j holds W0 column j in regs.
// Logits via precomputed ws0/wd0 — no warp reductions.
#define NB0 8
__global__ void __launch_bounds__(128) k_transform0(
        const float* __restrict__ x,
        const float* __restrict__ emb,
        const float* __restrict__ W0) {
    __shared__ float sfeat[D_IN][NB0];   // [k][node-in-tile]
    int j = threadIdx.x;
    int base = blockIdx.x * NB0;

    // stage features for 8 nodes (384 floats, 3 per thread), transposed
    for (int idx = j; idx < NB0 * D_IN; idx += 128) {
        int nn = idx / D_IN, k = idx - nn * D_IN;
        int node = base + nn;
        if (node < NNODES) {
            float v;
            if (k < F_IN) v = x[node * XCOLS + k];
            else {
                int cid = (int)x[node * XCOLS + F_IN];
                v = emb[cid * CELL_DIM + (k - F_IN)];
            }
            sfeat[k][nn] = v;
        }
    }

    float w[D_IN];
#pragma unroll
    for (int k = 0; k < D_IN; k++) w[k] = W0[k * 128 + j];
    __syncthreads();

    float acc[NB0];
#pragma unroll
    for (int nn = 0; nn < NB0; nn++) acc[nn] = 0.f;
#pragma unroll
    for (int k = 0; k < D_IN; k++) {
        float4 f0 = *(const float4*)&sfeat[k][0];
        float4 f1 = *(const float4*)&sfeat[k][4];
        acc[0] = fmaf(f0.x, w[k], acc[0]);
        acc[1] = fmaf(f0.y, w[k], acc[1]);
        acc[2] = fmaf(f0.z, w[k], acc[2]);
        acc[3] = fmaf(f0.w, w[k], acc[3]);
        acc[4] = fmaf(f1.x, w[k], acc[4]);
        acc[5] = fmaf(f1.y, w[k], acc[5]);
        acc[6] = fmaf(f1.z, w[k], acc[6]);
        acc[7] = fmaf(f1.w, w[k], acc[7]);
    }
#pragma unroll
    for (int nn = 0; nn < NB0; nn++) {
        int node = base + nn;
        if (node < NNODES) g_h0[node * 128 + j] = acc[nn];
    }
    // logits: 16 threads, one (node, head) each; 48-MAC dots from sfeat
    if (j < 2 * NB0) {
        int nn = j >> 1, h = j & 1;
        int node = base + nn;
        float as = 0.f, ad = 0.f;
#pragma unroll
        for (int k = 0; k < D_IN; k++) {
            float f = sfeat[k][nn];
            as = fmaf(f, g_ws0[k * 2 + h], as);
            ad = fmaf(f, g_wd0[k * 2 + h], ad);
        }
        if (node < NNODES) {
            g_as0[node * 2 + h] = as;
            g_ad0[node * 2 + h] = ad;
        }
    }
}

// ---------------- layer0 aggregation + LN/ELU + fused layer1 transform -------
// One warp per dst node, 8 warps/block. Lane L owns channels 4L..4L+3 of the
// 128-wide [head0|head1] row (lanes 0-15 head0, 16-31 head1). 2 chains.
__global__ void __launch_bounds__(256) k_agg0(
        const float* __restrict__ b0,
        const float* __restrict__ lng,
        const float* __restrict__ lnb,
        const float* __restrict__ W1,
        const float* __restrict__ a_s1,
        const float* __restrict__ a_d1) {
    __shared__ float sW1[64 * 64];       // 16 KB
    __shared__ float sa1[64], sd1[64];
    __shared__ float sy[8][64];
    int tid = threadIdx.x;
    for (int i = tid; i < 4096; i += 256) sW1[i] = W1[i];
    if (tid < 64) { sa1[tid] = a_s1[tid]; sd1[tid] = a_d1[tid]; }
    __syncthreads();

    int warp = tid >> 5, lane = tid & 31;
    int n = blockIdx.x * 8 + warp;
    if (n >= NNODES) return;

    const float2* as0v = (const float2*)g_as0;
    const float2 adv = ((const float2*)g_ad0)[n];
    int head = lane >> 4;
    int p0 = g_off[n], p1 = p0 + g_deg[n];

    float sP = 0.f, sQ = 0.f;
    float4 accP = make_float4(0.f, 0.f, 0.f, 0.f);
    float4 accQ = make_float4(0.f, 0.f, 0.f, 0.f);

    for (int base = p0; base < p1; base += 32) {
        int cnt = min(32, p1 - base);
        int srcs = (lane < cnt) ? g_csrc[base + lane] : 0;
        int k = 0;
        for (; k + 1 < cnt; k += 2) {
            int sa = __shfl_sync(0xffffffffu, srcs, k);
            int sb = __shfl_sync(0xffffffffu, srcs, k + 1);
            float2 asa = as0v[sa];
            float2 asb = as0v[sb];
            float4 ha = *(const float4*)(g_h0 + sa * 128 + lane * 4);
            float4 hb = *(const float4*)(g_h0 + sb * 128 + lane * 4);
            float pa = __expf(lrelu(head ? (asa.y + adv.y) : (asa.x + adv.x)));
            float pb = __expf(lrelu(head ? (asb.y + adv.y) : (asb.x + adv.x)));
            sP += pa; sQ += pb;
            accP.x = fmaf(pa, ha.x, accP.x);
            accP.y = fmaf(pa, ha.y, accP.y);
            accP.z = fmaf(pa, ha.z, accP.z);
            accP.w = fmaf(pa, ha.w, accP.w);
            accQ.x = fmaf(pb, hb.x, accQ.x);
            accQ.y = fmaf(pb, hb.y, accQ.y);
            accQ.z = fmaf(pb, hb.z, accQ.z);
            accQ.w = fmaf(pb, hb.w, accQ.w);
        }
        if (k < cnt) {
            int sa = __shfl_sync(0xffffffffu, srcs, k);
            float2 asa = as0v[sa];
            float4 ha = *(const float4*)(g_h0 + sa * 128 + lane * 4);
            float pa = __expf(lrelu(head ? (asa.y + adv.y) : (asa.x + adv.x)));
            sP += pa;
            accP.x = fmaf(pa, ha.x, accP.x);
            accP.y = fmaf(pa, ha.y, accP.y);
            accP.z = fmaf(pa, ha.z, accP.z);
            accP.w = fmaf(pa, ha.w, accP.w);
        }
    }
    float inv = 1.f / (sP + sQ);
    float4 r;
    r.x = (accP.x + accQ.x) * inv;
    r.y = (accP.y + accQ.y) * inv;
    r.z = (accP.z + accQ.z) * inv;
    r.w = (accP.w + accQ.w) * inv;

    // head mean across halves, + bias
    float4 o;
    o.x = __shfl_xor_sync(0xffffffffu, r.x, 16);
    o.y = __shfl_xor_sync(0xffffffffu, r.y, 16);
    o.z = __shfl_xor_sync(0xffffffffu, r.z, 16);
    o.w = __shfl_xor_sync(0xffffffffu, r.w, 16);
    int c4 = lane & 15;
    float4 bv = ((const float4*)b0)[c4];
    float4 v;
    v.x = 0.5f * (r.x + o.x) + bv.x;
    v.y = 0.5f * (r.y + o.y) + bv.y;
    v.z = 0.5f * (r.z + o.z) + bv.z;
    v.w = 0.5f * (r.w + o.w) + bv.w;

    // LayerNorm (each channel appears twice across the warp)
    float mu = warpSum(v.x + v.y + v.z + v.w) * (1.f / 128.f);
    float4 d = make_float4(v.x - mu, v.y - mu, v.z - mu, v.w - mu);
    float var = warpSum(d.x * d.x + d.y * d.y + d.z * d.z + d.w * d.w) * (1.f / 128.f);
    float rsv = rsqrtf(var + 1e-5f);
    float4 gv = ((const float4*)lng)[c4];
    float4 bb = ((const float4*)lnb)[c4];
    float4 y;
    y.x = d.x * rsv * gv.x + bb.x;
    y.y = d.y * rsv * gv.y + bb.y;
    y.z = d.z * rsv * gv.z + bb.z;
    y.w = d.w * rsv * gv.w + bb.w;
    y.x = y.x > 0.f ? y.x : expm1f(y.x);
    y.y = y.y > 0.f ? y.y : expm1f(y.y);
    y.z = y.z > 0.f ? y.z : expm1f(y.z);
    y.w = y.w > 0.f ? y.w : expm1f(y.w);

    // stage y[64] for this warp's node
    if (lane < 16) ((float4*)sy[warp])[c4] = y;
    __syncwarp();

    // fused layer1 transform: h1 = y @ W1; lane computes columns 2L, 2L+1
    float a0 = 0.f, a1 = 0.f;
#pragma unroll
    for (int k4 = 0; k4 < 16; k4++) {
        float4 y4 = ((const float4*)sy[warp])[k4];
        float2 w0 = ((const float2*)(sW1 + (4 * k4 + 0) * 64))[lane];
        float2 w1 = ((const float2*)(sW1 + (4 * k4 + 1) * 64))[lane];
        float2 w2 = ((const float2*)(sW1 + (4 * k4 + 2) * 64))[lane];
        float2 w3 = ((const float2*)(sW1 + (4 * k4 + 3) * 64))[lane];
        a0 = fmaf(y4.x, w0.x, a0); a1 = fmaf(y4.x, w0.y, a1);
        a0 = fmaf(y4.y, w1.x, a0); a1 = fmaf(y4.y, w1.y, a1);
        a0 = fmaf(y4.z, w2.x, a0); a1 = fmaf(y4.z, w2.y, a1);
        a0 = fmaf(y4.w, w3.x, a0); a1 = fmaf(y4.w, w3.y, a1);
    }
    ((float2*)(g_h1 + n * 64))[lane] = make_float2(a0, a1);
    float ts = warpSum(a0 * sa1[2 * lane] + a1 * sa1[2 * lane + 1]);
    float td = warpSum(a0 * sd1[2 * lane] + a1 * sd1[2 * lane + 1]);
    if (lane == 0) { g_as1[n] = ts; g_ad1[n] = td; }
}

// ---------------- layer1 aggregation -> output -------------------------------
// One warp per dst node, lane owns channels 2L..2L+1 (float2), 2 chains.
__global__ void __launch_bounds__(256) k_agg1(const float* __restrict__ b1,
                                              float* __restrict__ out) {
    int tid = threadIdx.x;
    int warp = tid >> 5, lane = tid & 31;
    int n = blockIdx.x * 8 + warp;
    if (n >= NNODES) return;
    float add = g_ad1[n];
    int p0 = g_off[n], p1 = p0 + g_deg[n];

    float sP = 0.f, sQ = 0.f;
    float2 accP = make_float2(0.f, 0.f);
    float2 accQ = make_float2(0.f, 0.f);

    for (int base = p0; base < p1; base += 32) {
        int cnt = min(32, p1 - base);
        int srcs = (lane < cnt) ? g_csrc[base + lane] : 0;
        int k = 0;
        for (; k + 1 < cnt; k += 2) {
            int sa = __shfl_sync(0xffffffffu, srcs, k);
            int sb = __shfl_sync(0xffffffffu, srcs, k + 1);
            float pa = __expf(lrelu(g_as1[sa] + add));
            float pb = __expf(lrelu(g_as1[sb] + add));
            float2 ha = *(const float2*)(g_h1 + sa * 64 + lane * 2);
            float2 hb = *(const float2*)(g_h1 + sb * 64 + lane * 2);
            sP += pa; sQ += pb;
            accP.x = fmaf(pa, ha.x, accP.x);
            accP.y = fmaf(pa, ha.y, accP.y);
            accQ.x = fmaf(pb, hb.x, accQ.x);
            accQ.y = fmaf(pb, hb.y, accQ.y);
        }
        if (k < cnt) {
            int sa = __shfl_sync(0xffffffffu, srcs, k);
            float pa = __expf(lrelu(g_as1[sa] + add));
            float2 ha = *(const float2*)(g_h1 + sa * 64 + lane * 2);
            sP += pa;
            accP.x = fmaf(pa, ha.x, accP.x);
            accP.y = fmaf(pa, ha.y, accP.y);
        }
    }
    float inv = 1.f / (sP + sQ);
    float2 bv = ((const float2*)b1)[lane];
    float2 o;
    o.x = (accP.x + accQ.x) * inv + bv.x;
    o.y = (accP.y + accQ.y) * inv + bv.y;
    ((float2*)(out + n * 64))[lane] = o;
}

// ---------------- launch -----------------------------------------------------
extern "C" void kernel_launch(void* const* d_in, const int* in_sizes, int n_in,
                              void* d_out, int out_size) {
    const float* x   = (const float*)d_in[0];
    const int*   ei  = (const int*)  d_in[1];
    const float* emb = (const float*)d_in[2];
    const float* W0  = (const float*)d_in[3];
    const float* as0 = (const float*)d_in[4];
    const float* ad0 = (const float*)d_in[5];
    const float* b0  = (const float*)d_in[6];
    const float* lng = (const float*)d_in[7];
    const float* lnb = (const float*)d_in[8];
    const float* W1  = (const float*)d_in[9];
    const float* as1 = (const float*)d_in[10];
    const float* ad1 = (const float*)d_in[11];
    const float* b1  = (const float*)d_in[12];
    float* out = (float*)d_out;

    void* degPtr = nullptr;
    cudaGetSymbolAddress(&degPtr, g_deg);
    cudaMemsetAsync(degPtr, 0, (NNODES + 1) * sizeof(int));

    k_count<<<(EALL + 255) / 256, 256>>>(ei);
    k_offsets<<<OFFB + 1, 256>>>(W0, as0, ad0);
    k_fill<<<(EALL + 255) / 256, 256>>>(ei);

    k_transform0<<<(NNODES + NB0 - 1) / NB0, 128>>>(x, emb, W0);
    k_agg0<<<(NNODES + 7) / 8, 256>>>(b0, lng, lnb, W1, as1, ad1);
    k_agg1<<<(NNODES + 7) / 8, 256>>>(b1, out);
}

// round 11
// speedup vs baseline: 1.5307x; 1.5307x over previous
#include <cuda_runtime.h>
#include <math.h>

#define NNODES 50000
#define NEDGES 800000
#define EALL   850000          // edges + self loops
#define F_IN   32
#define CELL_DIM 16
#define D_IN   48              // F_IN + CELL_DIM
#define XCOLS  33              // F_IN + 1 (cell id column)
#define C      64
#define NEG_SLOPE 0.2f
#define OFFB   ((NNODES + 255) / 256)    // 196 offset blocks

// ---------------- scratch ----------------------------------------------------
__device__ int   g_deg[NNODES + 1];      // [NNODES] doubles as global cursor
__device__ int   g_off[NNODES];
__device__ int   g_cursor[NNODES];
__device__ int   g_csrc[EALL];
__device__ float g_h0[NNODES * 128];     // layer0 transformed [N, head0|head1]
__device__ float g_as0[NNODES * 2];
__device__ float g_ad0[NNODES * 2];
__device__ float g_h1[NNODES * C];
__device__ float g_as1[NNODES];
__device__ float g_ad1[NNODES];
__device__ float g_ws0[D_IN * 2];        // W0 @ a_src0   [k][h]
__device__ float g_wd0[D_IN * 2];        // W0 @ a_dst0   [k][h]

__device__ __forceinline__ float warpSum(float v) {
#pragma unroll
    for (int o = 16; o; o >>= 1) v += __shfl_xor_sync(0xffffffffu, v, o);
    return v;
}

__device__ __forceinline__ float lrelu(float e) {
    return e > 0.f ? e : NEG_SLOPE * e;
}

// ---------------- CSR build --------------------------------------------------
__global__ void k_count(const int* __restrict__ ei) {
    int i = blockIdx.x * blockDim.x + threadIdx.x;
    if (i >= EALL) return;
    int d = (i < NEDGES) ? ei[NEDGES + i] : (i - NEDGES);
    atomicAdd(&g_deg[d], 1);
}

// Atomic segment assignment (order-independent); block OFFB additionally
// precomputes ws0/wd0 = W0 @ a_{src,dst}0 (folded to avoid an extra launch).
__global__ void k_offsets(const float* __restrict__ W0,
                          const float* __restrict__ as0,
                          const float* __restrict__ ad0) {
    int b = blockIdx.x, tid = threadIdx.x;
    if (b < OFFB) {
        int i = b * 256 + tid;
        if (i >= NNODES) return;
        int d = g_deg[i];
        int o = atomicAdd(&g_deg[NNODES], d);
        g_off[i] = o;
        g_cursor[i] = o;
    } else if (tid < 192) {
        int idx = tid % 96, which = tid / 96;       // 96 = D_IN*2
        int k = idx >> 1, h = idx & 1;
        const float* a = which ? ad0 : as0;
        float s = 0.f;
#pragma unroll
        for (int c = 0; c < 64; c++)
            s = fmaf(W0[k * 128 + h * 64 + c], a[h * 64 + c], s);
        if (which) g_wd0[idx] = s; else g_ws0[idx] = s;
    }
}

__global__ void k_fill(const int* __restrict__ ei) {
    int i = blockIdx.x * blockDim.x + threadIdx.x;
    if (i >= EALL) return;
    int s, d;
    if (i < NEDGES) { s = ei[i]; d = ei[NEDGES + i]; }
    else            { s = i - NEDGES; d = s; }
    int p = atomicAdd(&g_cursor[d], 1);
    g_csrc[p] = s;
}

// ---------------- layer0 node transform: feat[48] @ W0[48,128] ---------------
// One tile (8 nodes) per block; thread j holds W0 column j in registers.
// sfeat[nn][k] layout: staging stores are coalesced/conflict-free (R7 form).
// Logits via precomputed ws0/wd0 — no warp reductions.
#define NB0 8
__global__ void __launch_bounds__(128) k_transform0(
        const float* __restrict__ x,
        const float* __restrict__ emb,
        const float* __restrict__ W0) {
    __shared__ float sfeat[NB0][D_IN];   // [node-in-tile][k]
    int j = threadIdx.x;
    int base = blockIdx.x * NB0;

    // stage features for 8 nodes (384 floats, 3 per thread)
    for (int idx = j; idx < NB0 * D_IN; idx += 128) {
        int nn = idx / D_IN, k = idx - nn * D_IN;
        int node = base + nn;
        if (node < NNODES) {
            float v;
            if (k < F_IN) v = x[node * XCOLS + k];
            else {
                int cid = (int)x[node * XCOLS + F_IN];
                v = emb[cid * CELL_DIM + (k - F_IN)];
            }
            sfeat[nn][k] = v;
        }
    }

    float w[D_IN];
#pragma unroll
    for (int k = 0; k < D_IN; k++) w[k] = W0[k * 128 + j];
    __syncthreads();

    float acc[NB0];
#pragma unroll
    for (int nn = 0; nn < NB0; nn++) acc[nn] = 0.f;
#pragma unroll
    for (int k = 0; k < D_IN; k++) {
        acc[0] = fmaf(sfeat[0][k], w[k], acc[0]);
        acc[1] = fmaf(sfeat[1][k], w[k], acc[1]);
        acc[2] = fmaf(sfeat[2][k], w[k], acc[2]);
        acc[3] = fmaf(sfeat[3][k], w[k], acc[3]);
        acc[4] = fmaf(sfeat[4][k], w[k], acc[4]);
        acc[5] = fmaf(sfeat[5][k], w[k], acc[5]);
        acc[6] = fmaf(sfeat[6][k], w[k], acc[6]);
        acc[7] = fmaf(sfeat[7][k], w[k], acc[7]);
    }
#pragma unroll
    for (int nn = 0; nn < NB0; nn++) {
        int node = base + nn;
        if (node < NNODES) g_h0[node * 128 + j] = acc[nn];
    }
    // logits: 16 threads, one (node, head) each; 48-MAC dots from sfeat
    if (j < 2 * NB0) {
        int nn = j >> 1, h = j & 1;
        int node = base + nn;
        float as = 0.f, ad = 0.f;
#pragma unroll
        for (int k = 0; k < D_IN; k++) {
            float f = sfeat[nn][k];
            as = fmaf(f, g_ws0[k * 2 + h], as);
            ad = fmaf(f, g_wd0[k * 2 + h], ad);
        }
        if (node < NNODES) {
            g_as0[node * 2 + h] = as;
            g_ad0[node * 2 + h] = ad;
        }
    }
}

// ---------------- layer0 aggregation + LN/ELU + fused layer1 transform -------
// One warp per dst node, 8 warps/block. Lane L owns channels 4L..4L+3 of the
// 128-wide [head0|head1] row (lanes 0-15 head0, 16-31 head1). 2 chains.
__global__ void __launch_bounds__(256) k_agg0(
        const float* __restrict__ b0,
        const float* __restrict__ lng,
        const float* __restrict__ lnb,
        const float* __restrict__ W1,
        const float* __restrict__ a_s1,
        const float* __restrict__ a_d1) {
    __shared__ float sW1[64 * 64];       // 16 KB
    __shared__ float sa1[64], sd1[64];
    __shared__ float sy[8][64];
    int tid = threadIdx.x;
    for (int i = tid; i < 4096; i += 256) sW1[i] = W1[i];
    if (tid < 64) { sa1[tid] = a_s1[tid]; sd1[tid] = a_d1[tid]; }
    __syncthreads();

    int warp = tid >> 5, lane = tid & 31;
    int n = blockIdx.x * 8 + warp;
    if (n >= NNODES) return;

    const float2* as0v = (const float2*)g_as0;
    const float2 adv = ((const float2*)g_ad0)[n];
    int head = lane >> 4;
    int p0 = g_off[n], p1 = p0 + g_deg[n];

    float sP = 0.f, sQ = 0.f;
    float4 accP = make_float4(0.f, 0.f, 0.f, 0.f);
    float4 accQ = make_float4(0.f, 0.f, 0.f, 0.f);

    for (int base = p0; base < p1; base += 32) {
        int cnt = min(32, p1 - base);
        int srcs = (lane < cnt) ? g_csrc[base + lane] : 0;
        int k = 0;
        for (; k + 1 < cnt; k += 2) {
            int sa = __shfl_sync(0xffffffffu, srcs, k);
            int sb = __shfl_sync(0xffffffffu, srcs, k + 1);
            float2 asa = as0v[sa];
            float2 asb = as0v[sb];
            float4 ha = *(const float4*)(g_h0 + sa * 128 + lane * 4);
            float4 hb = *(const float4*)(g_h0 + sb * 128 + lane * 4);
            float pa = __expf(lrelu(head ? (asa.y + adv.y) : (asa.x + adv.x)));
            float pb = __expf(lrelu(head ? (asb.y + adv.y) : (asb.x + adv.x)));
            sP += pa; sQ += pb;
            accP.x = fmaf(pa, ha.x, accP.x);
            accP.y = fmaf(pa, ha.y, accP.y);
            accP.z = fmaf(pa, ha.z, accP.z);
            accP.w = fmaf(pa, ha.w, accP.w);
            accQ.x = fmaf(pb, hb.x, accQ.x);
            accQ.y = fmaf(pb, hb.y, accQ.y);
            accQ.z = fmaf(pb, hb.z, accQ.z);
            accQ.w = fmaf(pb, hb.w, accQ.w);
        }
        if (k < cnt) {
            int sa = __shfl_sync(0xffffffffu, srcs, k);
            float2 asa = as0v[sa];
            float4 ha = *(const float4*)(g_h0 + sa * 128 + lane * 4);
            float pa = __expf(lrelu(head ? (asa.y + adv.y) : (asa.x + adv.x)));
            sP += pa;
            accP.x = fmaf(pa, ha.x, accP.x);
            accP.y = fmaf(pa, ha.y, accP.y);
            accP.z = fmaf(pa, ha.z, accP.z);
            accP.w = fmaf(pa, ha.w, accP.w);
        }
    }
    float inv = 1.f / (sP + sQ);
    float4 r;
    r.x = (accP.x + accQ.x) * inv;
    r.y = (accP.y + accQ.y) * inv;
    r.z = (accP.z + accQ.z) * inv;
    r.w = (accP.w + accQ.w) * inv;

    // head mean across halves, + bias
    float4 o;
    o.x = __shfl_xor_sync(0xffffffffu, r.x, 16);
    o.y = __shfl_xor_sync(0xffffffffu, r.y, 16);
    o.z = __shfl_xor_sync(0xffffffffu, r.z, 16);
    o.w = __shfl_xor_sync(0xffffffffu, r.w, 16);
    int c4 = lane & 15;
    float4 bv = ((const float4*)b0)[c4];
    float4 v;
    v.x = 0.5f * (r.x + o.x) + bv.x;
    v.y = 0.5f * (r.y + o.y) + bv.y;
    v.z = 0.5f * (r.z + o.z) + bv.z;
    v.w = 0.5f * (r.w + o.w) + bv.w;

    // LayerNorm (each channel appears twice across the warp)
    float mu = warpSum(v.x + v.y + v.z + v.w) * (1.f / 128.f);
    float4 d = make_float4(v.x - mu, v.y - mu, v.z - mu, v.w - mu);
    float var = warpSum(d.x * d.x + d.y * d.y + d.z * d.z + d.w * d.w) * (1.f / 128.f);
    float rsv = rsqrtf(var + 1e-5f);
    float4 gv = ((const float4*)lng)[c4];
    float4 bb = ((const float4*)lnb)[c4];
    float4 y;
    y.x = d.x * rsv * gv.x + bb.x;
    y.y = d.y * rsv * gv.y + bb.y;
    y.z = d.z * rsv * gv.z + bb.z;
    y.w = d.w * rsv * gv.w + bb.w;
    y.x = y.x > 0.f ? y.x : expm1f(y.x);
    y.y = y.y > 0.f ? y.y : expm1f(y.y);
    y.z = y.z > 0.f ? y.z : expm1f(y.z);
    y.w = y.w > 0.f ? y.w : expm1f(y.w);

    // stage y[64] for this warp's node
    if (lane < 16) ((float4*)sy[warp])[c4] = y;
    __syncwarp();

    // fused layer1 transform: h1 = y @ W1; lane computes columns 2L, 2L+1
    float a0 = 0.f, a1 = 0.f;
#pragma unroll
    for (int k4 = 0; k4 < 16; k4++) {
        float4 y4 = ((const float4*)sy[warp])[k4];
        float2 w0 = ((const float2*)(sW1 + (4 * k4 + 0) * 64))[lane];
        float2 w1 = ((const float2*)(sW1 + (4 * k4 + 1) * 64))[lane];
        float2 w2 = ((const float2*)(sW1 + (4 * k4 + 2) * 64))[lane];
        float2 w3 = ((const float2*)(sW1 + (4 * k4 + 3) * 64))[lane];
        a0 = fmaf(y4.x, w0.x, a0); a1 = fmaf(y4.x, w0.y, a1);
        a0 = fmaf(y4.y, w1.x, a0); a1 = fmaf(y4.y, w1.y, a1);
        a0 = fmaf(y4.z, w2.x, a0); a1 = fmaf(y4.z, w2.y, a1);
        a0 = fmaf(y4.w, w3.x, a0); a1 = fmaf(y4.w, w3.y, a1);
    }
    ((float2*)(g_h1 + n * 64))[lane] = make_float2(a0, a1);
    float ts = warpSum(a0 * sa1[2 * lane] + a1 * sa1[2 * lane + 1]);
    float td = warpSum(a0 * sd1[2 * lane] + a1 * sd1[2 * lane + 1]);
    if (lane == 0) { g_as1[n] = ts; g_ad1[n] = td; }
}

// ---------------- layer1 aggregation -> output -------------------------------
// One warp per dst node, lane owns channels 2L..2L+1 (float2), 2 chains.
__global__ void __launch_bounds__(256) k_agg1(const float* __restrict__ b1,
                                              float* __restrict__ out) {
    int tid = threadIdx.x;
    int warp = tid >> 5, lane = tid & 31;
    int n = blockIdx.x * 8 + warp;
    if (n >= NNODES) return;
    float add = g_ad1[n];
    int p0 = g_off[n], p1 = p0 + g_deg[n];

    float sP = 0.f, sQ = 0.f;
    float2 accP = make_float2(0.f, 0.f);
    float2 accQ = make_float2(0.f, 0.f);

    for (int base = p0; base < p1; base += 32) {
        int cnt = min(32, p1 - base);
        int srcs = (lane < cnt) ? g_csrc[base + lane] : 0;
        int k = 0;
        for (; k + 1 < cnt; k += 2) {
            int sa = __shfl_sync(0xffffffffu, srcs, k);
            int sb = __shfl_sync(0xffffffffu, srcs, k + 1);
            float pa = __expf(lrelu(g_as1[sa] + add));
            float pb = __expf(lrelu(g_as1[sb] + add));
            float2 ha = *(const float2*)(g_h1 + sa * 64 + lane * 2);
            float2 hb = *(const float2*)(g_h1 + sb * 64 + lane * 2);
            sP += pa; sQ += pb;
            accP.x = fmaf(pa, ha.x, accP.x);
            accP.y = fmaf(pa, ha.y, accP.y);
            accQ.x = fmaf(pb, hb.x, accQ.x);
            accQ.y = fmaf(pb, hb.y, accQ.y);
        }
        if (k < cnt) {
            int sa = __shfl_sync(0xffffffffu, srcs, k);
            float pa = __expf(lrelu(g_as1[sa] + add));
            float2 ha = *(const float2*)(g_h1 + sa * 64 + lane * 2);
            sP += pa;
            accP.x = fmaf(pa, ha.x, accP.x);
            accP.y = fmaf(pa, ha.y, accP.y);
        }
    }
    float inv = 1.f / (sP + sQ);
    float2 bv = ((const float2*)b1)[lane];
    float2 o;
    o.x = (accP.x + accQ.x) * inv + bv.x;
    o.y = (accP.y + accQ.y) * inv + bv.y;
    ((float2*)(out + n * 64))[lane] = o;
}

// ---------------- launch -----------------------------------------------------
extern "C" void kernel_launch(void* const* d_in, const int* in_sizes, int n_in,
                              void* d_out, int out_size) {
    const float* x   = (const float*)d_in[0];
    const int*   ei  = (const int*)  d_in[1];
    const float* emb = (const float*)d_in[2];
    const float* W0  = (const float*)d_in[3];
    const float* as0 = (const float*)d_in[4];
    const float* ad0 = (const float*)d_in[5];
    const float* b0  = (const float*)d_in[6];
    const float* lng = (const float*)d_in[7];
    const float* lnb = (const float*)d_in[8];
    const float* W1  = (const float*)d_in[9];
    const float* as1 = (const float*)d_in[10];
    const float* ad1 = (const float*)d_in[11];
    const float* b1  = (const float*)d_in[12];
    float* out = (float*)d_out;

    void* degPtr = nullptr;
    cudaGetSymbolAddress(&degPtr, g_deg);
    cudaMemsetAsync(degPtr, 0, (NNODES + 1) * sizeof(int));

    k_count<<<(EALL + 255) / 256, 256>>>(ei);
    k_offsets<<<OFFB + 1, 256>>>(W0, as0, ad0);
    k_fill<<<(EALL + 255) / 256, 256>>>(ei);

    k_transform0<<<(NNODES + NB0 - 1) / NB0, 128>>>(x, emb, W0);
    k_agg0<<<(NNODES + 7) / 8, 256>>>(b0, lng, lnb, W1, as1, ad1);
    k_agg1<<<(NNODES + 7) / 8, 256>>>(b1, out);
}

// round 12
// speedup vs baseline: 1.6105x; 1.0521x over previous
#include <cuda_runtime.h>
#include <cuda_fp16.h>
#include <math.h>

#define NNODES 50000
#define NEDGES 800000
#define EALL   850000          // edges + self loops
#define F_IN   32
#define CELL_DIM 16
#define D_IN   48              // F_IN + CELL_DIM
#define XCOLS  33              // F_IN + 1 (cell id column)
#define C      64
#define NEG_SLOPE 0.2f
#define OFFB   ((NNODES + 255) / 256)    // 196 offset blocks
#define NB0    8
#define T0B    ((NNODES + NB0 - 1) / NB0)     // 6250 transform0 blocks
#define FILLB  ((EALL + 127) / 128)           // 6641 fill blocks

// ---------------- scratch ----------------------------------------------------
__device__ int    g_deg[NNODES + 1];     // [NNODES] doubles as global cursor
__device__ int    g_off[NNODES];
__device__ int    g_cursor[NNODES];
__device__ int    g_csrc[EALL];
__device__ __half g_h0[NNODES * 128];    // layer0 transformed, fp16 [N, h0|h1]
__device__ float  g_as0[NNODES * 2];
__device__ float  g_ad0[NNODES * 2];
__device__ __half g_h1[NNODES * C];      // layer1 transformed, fp16
__device__ float  g_as1[NNODES];
__device__ float  g_ad1[NNODES];
__device__ float  g_ws0[D_IN * 2];       // W0 @ a_src0   [k][h]
__device__ float  g_wd0[D_IN * 2];       // W0 @ a_dst0   [k][h]

__device__ __forceinline__ float warpSum(float v) {
#pragma unroll
    for (int o = 16; o; o >>= 1) v += __shfl_xor_sync(0xffffffffu, v, o);
    return v;
}

__device__ __forceinline__ float lrelu(float e) {
    return e > 0.f ? e : NEG_SLOPE * e;
}

// ---------------- CSR: count -------------------------------------------------
__global__ void k_count(const int* __restrict__ ei) {
    int i = blockIdx.x * blockDim.x + threadIdx.x;
    if (i >= EALL) return;
    int d = (i < NEDGES) ? ei[NEDGES + i] : (i - NEDGES);
    atomicAdd(&g_deg[d], 1);
}

// Atomic segment assignment (order-independent); block OFFB additionally
// precomputes ws0/wd0 = W0 @ a_{src,dst}0.
__global__ void k_offsets(const float* __restrict__ W0,
                          const float* __restrict__ as0,
                          const float* __restrict__ ad0) {
    int b = blockIdx.x, tid = threadIdx.x;
    if (b < OFFB) {
        int i = b * 256 + tid;
        if (i >= NNODES) return;
        int d = g_deg[i];
        int o = atomicAdd(&g_deg[NNODES], d);
        g_off[i] = o;
        g_cursor[i] = o;
    } else if (tid < 192) {
        int idx = tid % 96, which = tid / 96;       // 96 = D_IN*2
        int k = idx >> 1, h = idx & 1;
        const float* a = which ? ad0 : as0;
        float s = 0.f;
#pragma unroll
        for (int c = 0; c < 64; c++)
            s = fmaf(W0[k * 128 + h * 64 + c], a[h * 64 + c], s);
        if (which) g_wd0[idx] = s; else g_ws0[idx] = s;
    }
}

// ---------------- fused: transform0 (blocks < T0B)  ||  CSR fill -------------
// transform0: one 8-node tile per block; thread j holds W0 column j in regs;
// sfeat[nn][k] staging (conflict-free); logits via precomputed ws0/wd0.
// fill: independent of transform0, hidden under it in the same launch.
__global__ void __launch_bounds__(128) k_t0_fill(
        const int* __restrict__ ei,
        const float* __restrict__ x,
        const float* __restrict__ emb,
        const float* __restrict__ W0) {
    if (blockIdx.x >= T0B) {             // ---- fill branch ----
        int i = (blockIdx.x - T0B) * 128 + threadIdx.x;
        if (i >= EALL) return;
        int s, d;
        if (i < NEDGES) { s = ei[i]; d = ei[NEDGES + i]; }
        else            { s = i - NEDGES; d = s; }
        int p = atomicAdd(&g_cursor[d], 1);
        g_csrc[p] = s;
        return;
    }
    // ---- transform0 branch ----
    __shared__ float sfeat[NB0][D_IN];   // [node-in-tile][k]
    int j = threadIdx.x;
    int base = blockIdx.x * NB0;

    for (int idx = j; idx < NB0 * D_IN; idx += 128) {
        int nn = idx / D_IN, k = idx - nn * D_IN;
        int node = base + nn;
        if (node < NNODES) {
            float v;
            if (k < F_IN) v = x[node * XCOLS + k];
            else {
                int cid = (int)x[node * XCOLS + F_IN];
                v = emb[cid * CELL_DIM + (k - F_IN)];
            }
            sfeat[nn][k] = v;
        }
    }

    float w[D_IN];
#pragma unroll
    for (int k = 0; k < D_IN; k++) w[k] = W0[k * 128 + j];
    __syncthreads();

    float acc[NB0];
#pragma unroll
    for (int nn = 0; nn < NB0; nn++) acc[nn] = 0.f;
#pragma unroll
    for (int k = 0; k < D_IN; k++) {
        acc[0] = fmaf(sfeat[0][k], w[k], acc[0]);
        acc[1] = fmaf(sfeat[1][k], w[k], acc[1]);
        acc[2] = fmaf(sfeat[2][k], w[k], acc[2]);
        acc[3] = fmaf(sfeat[3][k], w[k], acc[3]);
        acc[4] = fmaf(sfeat[4][k], w[k], acc[4]);
        acc[5] = fmaf(sfeat[5][k], w[k], acc[5]);
        acc[6] = fmaf(sfeat[6][k], w[k], acc[6]);
        acc[7] = fmaf(sfeat[7][k], w[k], acc[7]);
    }
#pragma unroll
    for (int nn = 0; nn < NB0; nn++) {
        int node = base + nn;
        if (node < NNODES) g_h0[node * 128 + j] = __float2half_rn(acc[nn]);
    }
    // logits: 16 threads, one (node, head) each; fp32 throughout
    if (j < 2 * NB0) {
        int nn = j >> 1, h = j & 1;
        int node = base + nn;
        float as = 0.f, ad = 0.f;
#pragma unroll
        for (int k = 0; k < D_IN; k++) {
            float f = sfeat[nn][k];
            as = fmaf(f, g_ws0[k * 2 + h], as);
            ad = fmaf(f, g_wd0[k * 2 + h], ad);
        }
        if (node < NNODES) {
            g_as0[node * 2 + h] = as;
            g_ad0[node * 2 + h] = ad;
        }
    }
}

// ---------------- layer0 aggregation + LN/ELU + fused layer1 transform -------
// One warp per dst node, 8 warps/block. Lane L owns channels 4L..4L+3 of the
// 128-wide [head0|head1] row. h0 gathered as fp16 (8B/lane), 2 chains.
__global__ void __launch_bounds__(256) k_agg0(
        const float* __restrict__ b0,
        const float* __restrict__ lng,
        const float* __restrict__ lnb,
        const float* __restrict__ W1,
        const float* __restrict__ a_s1,
        const float* __restrict__ a_d1) {
    __shared__ float sW1[64 * 64];       // 16 KB
    __shared__ float sa1[64], sd1[64];
    __shared__ float sy[8][64];
    int tid = threadIdx.x;
    for (int i = tid; i < 4096; i += 256) sW1[i] = W1[i];
    if (tid < 64) { sa1[tid] = a_s1[tid]; sd1[tid] = a_d1[tid]; }
    __syncthreads();

    int warp = tid >> 5, lane = tid & 31;
    int n = blockIdx.x * 8 + warp;
    if (n >= NNODES) return;

    const float2* as0v = (const float2*)g_as0;
    const float2 adv = ((const float2*)g_ad0)[n];
    int head = lane >> 4;
    int p0 = g_off[n], p1 = p0 + g_deg[n];
    const uint2* h0v = (const uint2*)g_h0;      // 4 halves per lane

    float sP = 0.f, sQ = 0.f;
    float4 accP = make_float4(0.f, 0.f, 0.f, 0.f);
    float4 accQ = make_float4(0.f, 0.f, 0.f, 0.f);

    for (int base = p0; base < p1; base += 32) {
        int cnt = min(32, p1 - base);
        int srcs = (lane < cnt) ? g_csrc[base + lane] : 0;
        int k = 0;
        for (; k + 1 < cnt; k += 2) {
            int sa = __shfl_sync(0xffffffffu, srcs, k);
            int sb = __shfl_sync(0xffffffffu, srcs, k + 1);
            float2 asa = as0v[sa];
            float2 asb = as0v[sb];
            uint2 ra = h0v[sa * 32 + lane];
            uint2 rb = h0v[sb * 32 + lane];
            float pa = __expf(lrelu(head ? (asa.y + adv.y) : (asa.x + adv.x)));
            float pb = __expf(lrelu(head ? (asb.y + adv.y) : (asb.x + adv.x)));
            float2 a01 = __half22float2(*(const __half2*)&ra.x);
            float2 a23 = __half22float2(*(const __half2*)&ra.y);
            float2 b01 = __half22float2(*(const __half2*)&rb.x);
            float2 b23 = __half22float2(*(const __half2*)&rb.y);
            sP += pa; sQ += pb;
            accP.x = fmaf(pa, a01.x, accP.x);
            accP.y = fmaf(pa, a01.y, accP.y);
            accP.z = fmaf(pa, a23.x, accP.z);
            accP.w = fmaf(pa, a23.y, accP.w);
            accQ.x = fmaf(pb, b01.x, accQ.x);
            accQ.y = fmaf(pb, b01.y, accQ.y);
            accQ.z = fmaf(pb, b23.x, accQ.z);
            accQ.w = fmaf(pb, b23.y, accQ.w);
        }
        if (k < cnt) {
            int sa = __shfl_sync(0xffffffffu, srcs, k);
            float2 asa = as0v[sa];
            uint2 ra = h0v[sa * 32 + lane];
            float pa = __expf(lrelu(head ? (asa.y + adv.y) : (asa.x + adv.x)));
            float2 a01 = __half22float2(*(const __half2*)&ra.x);
            float2 a23 = __half22float2(*(const __half2*)&ra.y);
            sP += pa;
            accP.x = fmaf(pa, a01.x, accP.x);
            accP.y = fmaf(pa, a01.y, accP.y);
            accP.z = fmaf(pa, a23.x, accP.z);
            accP.w = fmaf(pa, a23.y, accP.w);
        }
    }
    float inv = 1.f / (sP + sQ);
    float4 r;
    r.x = (accP.x + accQ.x) * inv;
    r.y = (accP.y + accQ.y) * inv;
    r.z = (accP.z + accQ.z) * inv;
    r.w = (accP.w + accQ.w) * inv;

    // head mean across halves, + bias
    float4 o;
    o.x = __shfl_xor_sync(0xffffffffu, r.x, 16);
    o.y = __shfl_xor_sync(0xffffffffu, r.y, 16);
    o.z = __shfl_xor_sync(0xffffffffu, r.z, 16);
    o.w = __shfl_xor_sync(0xffffffffu, r.w, 16);
    int c4 = lane & 15;
    float4 bv = ((const float4*)b0)[c4];
    float4 v;
    v.x = 0.5f * (r.x + o.x) + bv.x;
    v.y = 0.5f * (r.y + o.y) + bv.y;
    v.z = 0.5f * (r.z + o.z) + bv.z;
    v.w = 0.5f * (r.w + o.w) + bv.w;

    // LayerNorm (each channel appears twice across the warp)
    float mu = warpSum(v.x + v.y + v.z + v.w) * (1.f / 128.f);
    float4 d = make_float4(v.x - mu, v.y - mu, v.z - mu, v.w - mu);
    float var = warpSum(d.x * d.x + d.y * d.y + d.z * d.z + d.w * d.w) * (1.f / 128.f);
    float rsv = rsqrtf(var + 1e-5f);
    float4 gv = ((const float4*)lng)[c4];
    float4 bb = ((const float4*)lnb)[c4];
    float4 y;
    y.x = d.x * rsv * gv.x + bb.x;
    y.y = d.y * rsv * gv.y + bb.y;
    y.z = d.z * rsv * gv.z + bb.z;
    y.w = d.w * rsv * gv.w + bb.w;
    y.x = y.x > 0.f ? y.x : expm1f(y.x);
    y.y = y.y > 0.f ? y.y : expm1f(y.y);
    y.z = y.z > 0.f ? y.z : expm1f(y.z);
    y.w = y.w > 0.f ? y.w : expm1f(y.w);

    // stage y[64] for this warp's node
    if (lane < 16) ((float4*)sy[warp])[c4] = y;
    __syncwarp();

    // fused layer1 transform: h1 = y @ W1; lane computes columns 2L, 2L+1
    float a0 = 0.f, a1 = 0.f;
#pragma unroll
    for (int k4 = 0; k4 < 16; k4++) {
        float4 y4 = ((const float4*)sy[warp])[k4];
        float2 w0 = ((const float2*)(sW1 + (4 * k4 + 0) * 64))[lane];
        float2 w1 = ((const float2*)(sW1 + (4 * k4 + 1) * 64))[lane];
        float2 w2 = ((const float2*)(sW1 + (4 * k4 + 2) * 64))[lane];
        float2 w3 = ((const float2*)(sW1 + (4 * k4 + 3) * 64))[lane];
        a0 = fmaf(y4.x, w0.x, a0); a1 = fmaf(y4.x, w0.y, a1);
        a0 = fmaf(y4.y, w1.x, a0); a1 = fmaf(y4.y, w1.y, a1);
        a0 = fmaf(y4.z, w2.x, a0); a1 = fmaf(y4.z, w2.y, a1);
        a0 = fmaf(y4.w, w3.x, a0); a1 = fmaf(y4.w, w3.y, a1);
    }
    ((__half2*)g_h1)[n * 32 + lane] = __floats2half2_rn(a0, a1);
    float ts = warpSum(a0 * sa1[2 * lane] + a1 * sa1[2 * lane + 1]);
    float td = warpSum(a0 * sd1[2 * lane] + a1 * sd1[2 * lane + 1]);
    if (lane == 0) { g_as1[n] = ts; g_ad1[n] = td; }
}

// ---------------- layer1 aggregation -> output -------------------------------
// One warp per dst node, lane owns channels 2L..2L+1 (half2 gather), 2 chains.
__global__ void __launch_bounds__(256) k_agg1(const float* __restrict__ b1,
                                              float* __restrict__ out) {
    int tid = threadIdx.x;
    int warp = tid >> 5, lane = tid & 31;
    int n = blockIdx.x * 8 + warp;
    if (n >= NNODES) return;
    float add = g_ad1[n];
    int p0 = g_off[n], p1 = p0 + g_deg[n];
    const __half2* h1v = (const __half2*)g_h1;

    float sP = 0.f, sQ = 0.f;
    float2 accP = make_float2(0.f, 0.f);
    float2 accQ = make_float2(0.f, 0.f);

    for (int base = p0; base < p1; base += 32) {
        int cnt = min(32, p1 - base);
        int srcs = (lane < cnt) ? g_csrc[base + lane] : 0;
        int k = 0;
        for (; k + 1 < cnt; k += 2) {
            int sa = __shfl_sync(0xffffffffu, srcs, k);
            int sb = __shfl_sync(0xffffffffu, srcs, k + 1);
            float pa = __expf(lrelu(g_as1[sa] + add));
            float pb = __expf(lrelu(g_as1[sb] + add));
            float2 ha = __half22float2(h1v[sa * 32 + lane]);
            float2 hb = __half22float2(h1v[sb * 32 + lane]);
            sP += pa; sQ += pb;
            accP.x = fmaf(pa, ha.x, accP.x);
            accP.y = fmaf(pa, ha.y, accP.y);
            accQ.x = fmaf(pb, hb.x, accQ.x);
            accQ.y = fmaf(pb, hb.y, accQ.y);
        }
        if (k < cnt) {
            int sa = __shfl_sync(0xffffffffu, srcs, k);
            float pa = __expf(lrelu(g_as1[sa] + add));
            float2 ha = __half22float2(h1v[sa * 32 + lane]);
            sP += pa;
            accP.x = fmaf(pa, ha.x, accP.x);
            accP.y = fmaf(pa, ha.y, accP.y);
        }
    }
    float inv = 1.f / (sP + sQ);
    float2 bv = ((const float2*)b1)[lane];
    float2 o;
    o.x = (accP.x + accQ.x) * inv + bv.x;
    o.y = (accP.y + accQ.y) * inv + bv.y;
    ((float2*)(out + n * 64))[lane] = o;
}

// ---------------- launch -----------------------------------------------------
extern "C" void kernel_launch(void* const* d_in, const int* in_sizes, int n_in,
                              void* d_out, int out_size) {
    const float* x   = (const float*)d_in[0];
    const int*   ei  = (const int*)  d_in[1];
    const float* emb = (const float*)d_in[2];
    const float* W0  = (const float*)d_in[3];
    const float* as0 = (const float*)d_in[4];
    const float* ad0 = (const float*)d_in[5];
    const float* b0  = (const float*)d_in[6];
    const float* lng = (const float*)d_in[7];
    const float* lnb = (const float*)d_in[8];
    const float* W1  = (const float*)d_in[9];
    const float* as1 = (const float*)d_in[10];
    const float* ad1 = (const float*)d_in[11];
    const float* b1  = (const float*)d_in[12];
    float* out = (float*)d_out;

    void* degPtr = nullptr;
    cudaGetSymbolAddress(&degPtr, g_deg);
    cudaMemsetAsync(degPtr, 0, (NNODES + 1) * sizeof(int));

    k_count<<<(EALL + 255) / 256, 256>>>(ei);
    k_offsets<<<OFFB + 1, 256>>>(W0, as0, ad0);
    k_t0_fill<<<T0B + FILLB, 128>>>(ei, x, emb, W0);
    k_agg0<<<(NNODES + 7) / 8, 256>>>(b0, lng, lnb, W1, as1, ad1);
    k_agg1<<<(NNODES + 7) / 8, 256>>>(b1, out);
}